// round 1
// baseline (speedup 1.0000x reference)
#include <cuda_runtime.h>

// Sparsemax over rows of a 16384 x 4096 fp32 matrix.
// One CTA per row. Sort-free exact tau via candidate filtering + Michelot.
//
//  tau* satisfies sum(max(x - tau, 0)) = 1 and tau* >= rowmax - 1,
//  so only elements > rowmax - 1 can be in the support. For Gaussian data
//  that's a handful of elements per row; Michelot's fixed-point iteration
//  on that candidate set converges exactly in a few steps (monotone support
//  shrinkage from any superset of the true support).

#define N_COLS  4096
#define THREADS 256
#define CAND_CAP 4096   // == N_COLS: overflow structurally impossible

__global__ __launch_bounds__(THREADS, 1)
void sparsemax_kernel(const float* __restrict__ x, float* __restrict__ out) {
    const int row  = blockIdx.x;
    const int tid  = threadIdx.x;
    const int lane = tid & 31;
    const int wid  = tid >> 5;

    const float4* xr = reinterpret_cast<const float4*>(x + (size_t)row * N_COLS);

    // ---- load 16 values per thread (coalesced float4) ----
    float4 v[4];
#pragma unroll
    for (int k = 0; k < 4; k++) v[k] = xr[tid + k * THREADS];

    // ---- row max: warp shfl reduce + cross-warp via shared ----
    float m = v[0].x;
#pragma unroll
    for (int k = 0; k < 4; k++) {
        m = fmaxf(m, fmaxf(fmaxf(v[k].x, v[k].y), fmaxf(v[k].z, v[k].w)));
    }
#pragma unroll
    for (int o = 16; o > 0; o >>= 1)
        m = fmaxf(m, __shfl_xor_sync(0xffffffffu, m, o));

    __shared__ float warp_max[THREADS / 32];
    __shared__ float sh_bcast;
    __shared__ int   sh_cnt;
    __shared__ float cand[CAND_CAP];

    if (lane == 0) warp_max[wid] = m;
    if (tid == 0)  sh_cnt = 0;
    __syncthreads();

    if (tid == 0) {
        float mm = warp_max[0];
#pragma unroll
        for (int i = 1; i < THREADS / 32; i++) mm = fmaxf(mm, warp_max[i]);
        sh_bcast = mm;
    }
    __syncthreads();

    const float rowmax = sh_bcast;
    const float thresh = rowmax - 1.0f;   // tau* >= thresh always

    // ---- gather candidates (x > rowmax - 1) into shared ----
#pragma unroll
    for (int k = 0; k < 4; k++) {
        float vals[4] = {v[k].x, v[k].y, v[k].z, v[k].w};
#pragma unroll
        for (int j = 0; j < 4; j++) {
            if (vals[j] > thresh) {
                int p = atomicAdd(&sh_cnt, 1);
                cand[p] = vals[j];
            }
        }
    }
    __syncthreads();

    // ---- warp 0: Michelot fixed-point on the (tiny) candidate set ----
    if (wid == 0) {
        const int n = sh_cnt;       // >= 1 (rowmax itself)
        float t = thresh;           // support(thresh) == all candidates
        int c_prev = -1;
        for (int iter = 0; iter <= CAND_CAP; iter++) {
            float s = 0.0f;
            int   c = 0;
            for (int i = lane; i < n; i += 32) {
                float z = cand[i];
                if (z > t) { s += z; c++; }
            }
#pragma unroll
            for (int o = 16; o > 0; o >>= 1) {
                s += __shfl_xor_sync(0xffffffffu, s, o);
                c += __shfl_xor_sync(0xffffffffu, c, o);
            }
            if (c == c_prev) break;     // support stabilized -> exact tau
            t = (s - 1.0f) / (float)c;  // c >= 1 (rowmax always in support)
            c_prev = c;
        }
        if (lane == 0) sh_bcast = t;
    }
    __syncthreads();
    const float tau = sh_bcast;

    // ---- write max(x - tau, 0), vectorized ----
    float4* orow = reinterpret_cast<float4*>(out + (size_t)row * N_COLS);
#pragma unroll
    for (int k = 0; k < 4; k++) {
        float4 o;
        o.x = fmaxf(v[k].x - tau, 0.0f);
        o.y = fmaxf(v[k].y - tau, 0.0f);
        o.z = fmaxf(v[k].z - tau, 0.0f);
        o.w = fmaxf(v[k].w - tau, 0.0f);
        orow[tid + k * THREADS] = o;
    }
}

extern "C" void kernel_launch(void* const* d_in, const int* in_sizes, int n_in,
                              void* d_out, int out_size) {
    const float* x = (const float*)d_in[0];
    float* out = (float*)d_out;
    const int rows = in_sizes[0] / N_COLS;   // 16384
    sparsemax_kernel<<<rows, THREADS>>>(x, out);
}